// round 4
// baseline (speedup 1.0000x reference)
#include <cuda_runtime.h>
#include <stdint.h>

#define IMGD   192
#define PATCHD 96
#define PVOX   (PATCHD*PATCHD*PATCHD)         // 884736
#define VVOX   (IMGD*IMGD*IMGD)               // 7077888
#define K_PRE  1000
#define MAX_OUT 100
#define NBINS  65536
#define CAND_CAP 2048
#define SCORE_THR 0.01f
#define MIN_SIZE  0.01f
#define IOU_THR   0.1f
#define CLS_OFF   384.0f   // 2.0 * 192.0

// ---------------- device scratch (no allocations allowed) ----------------
__device__ unsigned int       g_hist[NBINS];
__device__ unsigned int       g_cand_count;
__device__ int                g_thresh_bin;
__device__ unsigned long long g_cands[CAND_CAP];

__device__ __forceinline__ unsigned fkey(float f) {
    unsigned u = __float_as_uint(f);
    return (u & 0x80000000u) ? ~u : (u | 0x80000000u);
}

// ---------------- seg ensemble kernel (closed-form coverage, float4) ----------------
__global__ void seg_kernel(const float* __restrict__ tiles,
                           const float* __restrict__ w,
                           float* __restrict__ out,
                           int C) {
    int v4 = blockIdx.x * blockDim.x + threadIdx.x;   // float4-group index
    if (v4 >= VVOX / 4) return;
    int zq = v4 % (IMGD / 4);
    int t2 = v4 / (IMGD / 4);
    int y  = t2 % IMGD;
    int x  = t2 / IMGD;
    int z  = zq * 4;

    int ix = (x >= 96) ? 2 : ((x >= 48) ? 1 : 0);
    int iy = (y >= 96) ? 2 : ((y >= 48) ? 1 : 0);
    int iz = (z >= 96) ? 2 : ((z >= 48) ? 1 : 0);
    bool two_x = (x >= 48) && (x < 144);
    bool two_y = (y >= 48) && (y < 144);
    bool two_z = (z >= 48) && (z < 144);

    int lx = x - ix * 48, ly = y - iy * 48, lz = z - iz * 48;
    int li = (lx * PATCHD + ly) * PATCHD + lz;

    float4 ws = make_float4(0.f, 0.f, 0.f, 0.f);
    float4 wl = make_float4(0.f, 0.f, 0.f, 0.f);
    #pragma unroll
    for (int a = 0; a < 2; a++) {
        if (a == 1 && !two_x) break;
        int xx = lx + a * 48;
        #pragma unroll
        for (int b = 0; b < 2; b++) {
            if (b == 1 && !two_y) break;
            int yy = ly + b * 48;
            #pragma unroll
            for (int cdim = 0; cdim < 2; cdim++) {
                if (cdim == 1 && !two_z) break;
                int zz = lz + cdim * 48;
                float4 wv = *reinterpret_cast<const float4*>(
                    w + (xx * PATCHD + yy) * PATCHD + zz);
                ws.x += wv.x; ws.y += wv.y; ws.z += wv.z; ws.w += wv.w;
                if (a == 0 && b == 0 && cdim == 0) wl = wv;
            }
        }
    }

    int tlast = ix * 9 + iy * 3 + iz;
    int v = v4 * 4;
    float4 inv = make_float4(wl.x / ws.x, wl.y / ws.y, wl.z / ws.z, wl.w / ws.w);
    for (int c = 0; c < C; c++) {
        float4 tv = *reinterpret_cast<const float4*>(
            tiles + (size_t)(tlast * C + c) * PVOX + li);
        float4 o;
        o.x = tv.x * inv.x; o.y = tv.y * inv.y;
        o.z = tv.z * inv.z; o.w = tv.w * inv.w;
        *reinterpret_cast<float4*>(out + (size_t)c * VVOX + v) = o;
    }
}

// ---------------- top-K selection ----------------
__global__ void hist_kernel(const float* __restrict__ bb, int N) {
    int i = blockIdx.x * blockDim.x + threadIdx.x;
    if (i >= N) return;
    float s = __ldg(bb + (size_t)i * 7 + 6);
    atomicAdd(&g_hist[fkey(s) >> 16], 1u);
}

__global__ void thresh_kernel() {
    __shared__ unsigned csum[1024];
    int tid = threadIdx.x;
    unsigned s = 0;
    int base = tid * 64;
    #pragma unroll 4
    for (int b = 0; b < 64; b++) s += g_hist[base + b];
    csum[tid] = s;
    __syncthreads();
    for (int off = 1; off < 1024; off <<= 1) {
        unsigned v = (tid + off < 1024) ? csum[tid + off] : 0u;
        __syncthreads();
        csum[tid] += v;
        __syncthreads();
    }
    if (csum[tid] >= K_PRE && (tid == 1023 || csum[tid + 1] < K_PRE)) {
        unsigned acc = (tid == 1023) ? 0u : csum[tid + 1];
        int bin = base;
        for (int b = 63; b >= 0; b--) {
            acc += g_hist[base + b];
            if (acc >= K_PRE) { bin = base + b; break; }
        }
        g_thresh_bin = bin;
    }
}

__global__ void gather_kernel(const float* __restrict__ bb, int N) {
    int i = blockIdx.x * blockDim.x + threadIdx.x;
    if (i >= N) return;
    float s = __ldg(bb + (size_t)i * 7 + 6);
    unsigned key = fkey(s);
    if ((int)(key >> 16) >= g_thresh_bin) {
        unsigned pos = atomicAdd(&g_cand_count, 1u);
        if (pos < CAND_CAP)
            g_cands[pos] = ((unsigned long long)key << 32) | (unsigned)(~(unsigned)i);
    }
}

// ---------------- fused sort + prep + NMS + output (one 1024-thread block) ----------------
struct DetSmem {
    unsigned long long skey[CAND_CAP];   // 16 KB
    float sbox [K_PRE * 6];              // 24 KB (clipped, un-offset)
    float sobox[K_PRE * 6];              // 24 KB (clipped + class offset)
    float ssc  [K_PRE];                  //  4 KB
    int   slab [K_PRE];                  //  4 KB
    unsigned keep[32];
    int kept[MAX_OUT];
    int s_nk;
    int s_cur;
    int s_next;
};

__global__ void det_kernel(const float* __restrict__ bb,
                           const int* __restrict__ labels,
                           float* __restrict__ dets,   // [100,8]
                           float* __restrict__ labs) { // [100]
    extern __shared__ char smraw[];
    DetSmem* sm = reinterpret_cast<DetSmem*>(smraw);
    int tid = threadIdx.x;

    // --- load + pad candidates ---
    unsigned n = g_cand_count;
    if (n > CAND_CAP) n = CAND_CAP;
    for (int i = tid; i < CAND_CAP; i += 1024)
        sm->skey[i] = (i < (int)n) ? g_cands[i] : 0ull;
    if (tid < 32) sm->keep[tid] = 0u;
    if (tid == 0) { sm->s_nk = 0; sm->s_next = 0; sm->s_cur = -1; }
    __syncthreads();

    // --- bitonic sort descending (2048 keys) ---
    for (int k = 2; k <= CAND_CAP; k <<= 1) {
        for (int j = k >> 1; j > 0; j >>= 1) {
            for (int i = tid; i < CAND_CAP; i += 1024) {
                int l = i ^ j;
                if (l > i) {
                    unsigned long long a = sm->skey[i], b = sm->skey[l];
                    bool descRegion = ((i & k) == 0);
                    bool doSwap = descRegion ? (a < b) : (a > b);
                    if (doSwap) { sm->skey[i] = b; sm->skey[l] = a; }
                }
            }
            __syncthreads();
        }
    }

    // --- prep top-1000: clip, validity, offset boxes ---
    if (tid < K_PRE) {
        int r = tid;
        unsigned idx = ~((unsigned)sm->skey[r]);
        const float* p = bb + (size_t)idx * 7;
        float sc = __ldg(p + 6);
        int lb = __ldg(labels + idx);
        float off = (float)lb * CLS_OFF;
        bool valid = sc > SCORE_THR;
        #pragma unroll
        for (int d = 0; d < 3; d++) {
            float lo = fminf(fmaxf(__ldg(p + d),     0.0f), (float)IMGD);
            float hi = fminf(fmaxf(__ldg(p + d + 3), 0.0f), (float)IMGD);
            sm->sbox [r*6 + d]     = lo;
            sm->sbox [r*6 + d + 3] = hi;
            sm->sobox[r*6 + d]     = lo + off;
            sm->sobox[r*6 + d + 3] = hi + off;
            valid = valid && ((hi - lo) >= MIN_SIZE);
        }
        sm->ssc[r] = sc;
        sm->slab[r] = lb;
        if (valid) atomicOr(&sm->keep[r >> 5], 1u << (r & 31));
    }
    __syncthreads();

    // --- greedy NMS, block-parallel suppression, early exit at 100 kept ---
    for (;;) {
        if (tid == 0) {
            int i = sm->s_next;
            int found = -1;
            int wi = i >> 5;
            unsigned word = sm->keep[wi] & (0xFFFFFFFFu << (i & 31));
            for (;;) {
                if (word) { found = wi * 32 + __ffs(word) - 1; break; }
                if (++wi >= 32) break;
                word = sm->keep[wi];
            }
            sm->s_cur = found;
            if (found >= 0) {
                sm->kept[sm->s_nk] = found;
                sm->s_nk++;
                sm->s_next = found + 1;
            }
        }
        __syncthreads();
        int i = sm->s_cur;
        int nk = sm->s_nk;
        if (i < 0 || nk >= MAX_OUT) break;

        int j = i + 1 + tid;
        if (j < K_PRE && ((sm->keep[j >> 5] >> (j & 31)) & 1u)) {
            float a0 = sm->sobox[i*6+0], a1 = sm->sobox[i*6+1], a2 = sm->sobox[i*6+2];
            float a3 = sm->sobox[i*6+3], a4 = sm->sobox[i*6+4], a5 = sm->sobox[i*6+5];
            float va = ((a3 - a0) * (a4 - a1)) * (a5 - a2);
            float b0 = sm->sobox[j*6+0], b1 = sm->sobox[j*6+1], b2 = sm->sobox[j*6+2];
            float b3 = sm->sobox[j*6+3], b4 = sm->sobox[j*6+4], b5 = sm->sobox[j*6+5];
            float cx = fmaxf(fminf(a3, b3) - fmaxf(a0, b0), 0.0f);
            float cy = fmaxf(fminf(a4, b4) - fmaxf(a1, b1), 0.0f);
            float cz = fmaxf(fminf(a5, b5) - fmaxf(a2, b2), 0.0f);
            float inter = (cx * cy) * cz;
            float vb = ((b3 - b0) * (b4 - b1)) * (b5 - b2);
            float uni = fmaxf(va + vb - inter, 1e-6f);
            if (inter / uni > IOU_THR)
                atomicAnd(&sm->keep[j >> 5], ~(1u << (j & 31)));
        }
        __syncthreads();
    }

    // --- emit ---
    int nk = sm->s_nk;
    if (nk > MAX_OUT) nk = MAX_OUT;
    for (int r = tid; r < MAX_OUT; r += 1024) {
        if (r < nk) {
            int i = sm->kept[r];
            #pragma unroll
            for (int d = 0; d < 6; d++) dets[r*8 + d] = sm->sbox[i*6 + d];
            float s = sm->ssc[i];
            dets[r*8 + 6] = s;
            dets[r*8 + 7] = s;
            labs[r] = (float)sm->slab[i];
        } else {
            #pragma unroll
            for (int d = 0; d < 8; d++) dets[r*8 + d] = 0.0f;
            labs[r] = -1.0f;
        }
    }
}

// ---------------- launch (single stream, graph-capture safe) ----------------
extern "C" void kernel_launch(void* const* d_in, const int* in_sizes, int n_in,
                              void* d_out, int out_size) {
    const float* tiles  = (const float*)d_in[0];
    const float* w      = (const float*)d_in[1];
    const float* bb     = (const float*)d_in[2];
    const int*   labels = (const int*)  d_in[3];

    int T = in_sizes[4] / 3;
    int C = in_sizes[0] / (T * PVOX);
    int N = in_sizes[2] / 7;
    float* out = (float*)d_out;

    cudaFuncSetAttribute(det_kernel,
        cudaFuncAttributeMaxDynamicSharedMemorySize, (int)sizeof(DetSmem));

    void* hptr = nullptr; cudaGetSymbolAddress(&hptr, g_hist);
    void* cptr = nullptr; cudaGetSymbolAddress(&cptr, g_cand_count);
    cudaMemsetAsync(hptr, 0, NBINS * sizeof(unsigned));
    cudaMemsetAsync(cptr, 0, sizeof(unsigned));

    size_t seg_elems = (size_t)C * VVOX;

    hist_kernel<<<(N + 255) / 256, 256>>>(bb, N);
    thresh_kernel<<<1, 1024>>>();
    gather_kernel<<<(N + 255) / 256, 256>>>(bb, N);
    det_kernel<<<1, 1024, sizeof(DetSmem)>>>(
        bb, labels, out + seg_elems, out + seg_elems + MAX_OUT * 8);

    seg_kernel<<<(VVOX / 4 + 255) / 256, 256>>>(tiles, w, out, C);
}

// round 7
// speedup vs baseline: 1.3106x; 1.3106x over previous
#include <cuda_runtime.h>
#include <stdint.h>

#define IMGD   192
#define PATCHD 96
#define PVOX   (PATCHD*PATCHD*PATCHD)         // 884736
#define VVOX   (IMGD*IMGD*IMGD)               // 7077888
#define K_PRE  1000
#define MAX_OUT 100
#define NBINS  65536
#define CAND_CAP 2048
#define SCORE_THR 0.01f
#define MIN_SIZE  0.01f
#define IOU_THR   0.1f
#define CLS_OFF   384.0f   // 2.0 * 192.0

// ---------------- device scratch (no allocations allowed) ----------------
__device__ unsigned int       g_hist[NBINS];
__device__ unsigned int       g_cand_count;
__device__ int                g_thresh_bin;
__device__ unsigned long long g_cands[CAND_CAP];
__device__ float              g_box [K_PRE*6];
__device__ float              g_obox[K_PRE*6];
__device__ float              g_sc  [K_PRE];
__device__ int                g_lab [K_PRE];
__device__ unsigned int       g_validmask[32];
__device__ unsigned int       g_sup [K_PRE*32];

__device__ __forceinline__ unsigned fkey(float f) {
    unsigned u = __float_as_uint(f);
    return (u & 0x80000000u) ? ~u : (u | 0x80000000u);
}

// ---------------- seg ensemble kernel (closed-form coverage, float4) ----------------
__global__ void seg_kernel(const float* __restrict__ tiles,
                           const float* __restrict__ w,
                           float* __restrict__ out,
                           int C) {
    int v4 = blockIdx.x * blockDim.x + threadIdx.x;   // float4-group index
    if (v4 >= VVOX / 4) return;
    int zq = v4 % (IMGD / 4);
    int t2 = v4 / (IMGD / 4);
    int y  = t2 % IMGD;
    int x  = t2 / IMGD;
    int z  = zq * 4;

    int ix = (x >= 96) ? 2 : ((x >= 48) ? 1 : 0);
    int iy = (y >= 96) ? 2 : ((y >= 48) ? 1 : 0);
    int iz = (z >= 96) ? 2 : ((z >= 48) ? 1 : 0);
    bool two_x = (x >= 48) && (x < 144);
    bool two_y = (y >= 48) && (y < 144);
    bool two_z = (z >= 48) && (z < 144);

    int lx = x - ix * 48, ly = y - iy * 48, lz = z - iz * 48;
    int li = (lx * PATCHD + ly) * PATCHD + lz;

    float4 ws = make_float4(0.f, 0.f, 0.f, 0.f);
    float4 wl = make_float4(0.f, 0.f, 0.f, 0.f);
    #pragma unroll
    for (int a = 0; a < 2; a++) {
        if (a == 1 && !two_x) break;
        int xx = lx + a * 48;
        #pragma unroll
        for (int b = 0; b < 2; b++) {
            if (b == 1 && !two_y) break;
            int yy = ly + b * 48;
            #pragma unroll
            for (int cdim = 0; cdim < 2; cdim++) {
                if (cdim == 1 && !two_z) break;
                int zz = lz + cdim * 48;
                float4 wv = *reinterpret_cast<const float4*>(
                    w + (xx * PATCHD + yy) * PATCHD + zz);
                ws.x += wv.x; ws.y += wv.y; ws.z += wv.z; ws.w += wv.w;
                if (a == 0 && b == 0 && cdim == 0) wl = wv;
            }
        }
    }

    int tlast = ix * 9 + iy * 3 + iz;
    int v = v4 * 4;
    float4 inv = make_float4(wl.x / ws.x, wl.y / ws.y, wl.z / ws.z, wl.w / ws.w);
    for (int c = 0; c < C; c++) {
        float4 tv = *reinterpret_cast<const float4*>(
            tiles + (size_t)(tlast * C + c) * PVOX + li);
        float4 o;
        o.x = tv.x * inv.x; o.y = tv.y * inv.y;
        o.z = tv.z * inv.z; o.w = tv.w * inv.w;
        *reinterpret_cast<float4*>(out + (size_t)c * VVOX + v) = o;
    }
}

// ---------------- top-K selection ----------------
__global__ void hist_kernel(const float* __restrict__ bb, int N) {
    int i = blockIdx.x * blockDim.x + threadIdx.x;
    if (i >= N) return;
    float s = __ldg(bb + (size_t)i * 7 + 6);
    atomicAdd(&g_hist[fkey(s) >> 16], 1u);
}

__global__ void thresh_kernel() {
    __shared__ unsigned csum[1024];
    int tid = threadIdx.x;
    unsigned s = 0;
    int base = tid * 64;
    #pragma unroll 4
    for (int b = 0; b < 64; b++) s += g_hist[base + b];
    csum[tid] = s;
    __syncthreads();
    for (int off = 1; off < 1024; off <<= 1) {
        unsigned v = (tid + off < 1024) ? csum[tid + off] : 0u;
        __syncthreads();
        csum[tid] += v;
        __syncthreads();
    }
    if (csum[tid] >= K_PRE && (tid == 1023 || csum[tid + 1] < K_PRE)) {
        unsigned acc = (tid == 1023) ? 0u : csum[tid + 1];
        int bin = base;
        for (int b = 63; b >= 0; b--) {
            acc += g_hist[base + b];
            if (acc >= K_PRE) { bin = base + b; break; }
        }
        g_thresh_bin = bin;
    }
}

__global__ void gather_kernel(const float* __restrict__ bb, int N) {
    int i = blockIdx.x * blockDim.x + threadIdx.x;
    if (i >= N) return;
    float s = __ldg(bb + (size_t)i * 7 + 6);
    unsigned key = fkey(s);
    if ((int)(key >> 16) >= g_thresh_bin) {
        unsigned pos = atomicAdd(&g_cand_count, 1u);
        if (pos < CAND_CAP)
            g_cands[pos] = ((unsigned long long)key << 32) | (unsigned)(~(unsigned)i);
    }
}

// ---------------- rank by counting + prep (one warp per candidate) ----------------
// rank = #keys strictly greater (keys unique -> bijection). Candidates with
// rank < K_PRE are exactly the sorted top-1000; prep them directly at slot rank.
__global__ void rank_kernel(const float* __restrict__ bb,
                            const int* __restrict__ labels) {
    int gw   = (blockIdx.x * blockDim.x + threadIdx.x) >> 5;
    int lane = threadIdx.x & 31;
    unsigned count = g_cand_count;
    if (count > CAND_CAP) count = CAND_CAP;
    if (gw >= (int)count) return;

    unsigned long long key = g_cands[gw];
    int r = 0;
    for (int k = lane; k < (int)count; k += 32)
        r += (g_cands[k] > key) ? 1 : 0;
    #pragma unroll
    for (int o = 16; o > 0; o >>= 1) r += __shfl_down_sync(0xffffffffu, r, o);
    r = __shfl_sync(0xffffffffu, r, 0);
    if (r >= K_PRE) return;

    if (lane == 0) {
        unsigned idx = ~((unsigned)key);
        const float* p = bb + (size_t)idx * 7;
        float sc = __ldg(p + 6);
        int lb = __ldg(labels + idx);
        float off = (float)lb * CLS_OFF;
        bool valid = sc > SCORE_THR;
        #pragma unroll
        for (int d = 0; d < 3; d++) {
            float lo = fminf(fmaxf(__ldg(p + d),     0.0f), (float)IMGD);
            float hi = fminf(fmaxf(__ldg(p + d + 3), 0.0f), (float)IMGD);
            g_box [r*6 + d]     = lo;
            g_box [r*6 + d + 3] = hi;
            g_obox[r*6 + d]     = lo + off;
            g_obox[r*6 + d + 3] = hi + off;
            valid = valid && ((hi - lo) >= MIN_SIZE);
        }
        g_sc[r] = sc;
        g_lab[r] = lb;
        if (valid) atomicOr(&g_validmask[r >> 5], 1u << (r & 31));
    }
}

// ---------------- suppression bitmask (chip-wide parallel) ----------------
__global__ void sup_kernel() {
    int i = blockIdx.x;          // 0..K_PRE-1
    int t = threadIdx.x;         // 0..31 -> word index
    float a0 = g_obox[i*6+0], a1 = g_obox[i*6+1], a2 = g_obox[i*6+2];
    float a3 = g_obox[i*6+3], a4 = g_obox[i*6+4], a5 = g_obox[i*6+5];
    float va = ((a3 - a0) * (a4 - a1)) * (a5 - a2);
    unsigned m = 0;
    int base = t * 32;
    #pragma unroll 4
    for (int b = 0; b < 32; b++) {
        int j = base + b;
        if (j < K_PRE && j > i) {
            float b0 = g_obox[j*6+0], b1 = g_obox[j*6+1], b2 = g_obox[j*6+2];
            float b3 = g_obox[j*6+3], b4 = g_obox[j*6+4], b5 = g_obox[j*6+5];
            float cx = fmaxf(fminf(a3, b3) - fmaxf(a0, b0), 0.0f);
            float cy = fmaxf(fminf(a4, b4) - fmaxf(a1, b1), 0.0f);
            float cz = fmaxf(fminf(a5, b5) - fmaxf(a2, b2), 0.0f);
            float inter = (cx * cy) * cz;
            float vb = ((b3 - b0) * (b4 - b1)) * (b5 - b2);
            float uni = fmaxf(va + vb - inter, 1e-6f);
            if (inter / uni > IOU_THR) m |= (1u << b);
        }
    }
    g_sup[i*32 + t] = m;
}

// ---------------- sequential NMS + output (1 warp, round-1 validated) ----------------
__global__ void final_kernel(float* __restrict__ dets,   // [100,8]
                             float* __restrict__ labs) { // [100]
    int lane = threadIdx.x;      // 0..31
    unsigned keepw = g_validmask[lane];
    __shared__ int kept[MAX_OUT];
    int nk = 0;
    for (int i = 0; i < K_PRE; i++) {
        unsigned w = __shfl_sync(0xffffffffu, keepw, i >> 5);
        if ((w >> (i & 31)) & 1u) {
            if (lane == 0) kept[nk] = i;
            nk++;
            if (nk == MAX_OUT) break;
            keepw &= ~g_sup[i*32 + lane];
        }
    }
    __syncwarp();
    for (int r = lane; r < MAX_OUT; r += 32) {
        if (r < nk) {
            int i = kept[r];
            #pragma unroll
            for (int d = 0; d < 6; d++) dets[r*8 + d] = g_box[i*6 + d];
            float s = g_sc[i];
            dets[r*8 + 6] = s;
            dets[r*8 + 7] = s;
            labs[r] = (float)g_lab[i];
        } else {
            #pragma unroll
            for (int d = 0; d < 8; d++) dets[r*8 + d] = 0.0f;
            labs[r] = -1.0f;
        }
    }
}

// ---------------- launch (single stream, graph-capture safe) ----------------
extern "C" void kernel_launch(void* const* d_in, const int* in_sizes, int n_in,
                              void* d_out, int out_size) {
    const float* tiles  = (const float*)d_in[0];
    const float* w      = (const float*)d_in[1];
    const float* bb     = (const float*)d_in[2];
    const int*   labels = (const int*)  d_in[3];

    int T = in_sizes[4] / 3;
    int C = in_sizes[0] / (T * PVOX);
    int N = in_sizes[2] / 7;
    float* out = (float*)d_out;

    void* hptr = nullptr; cudaGetSymbolAddress(&hptr, g_hist);
    void* cptr = nullptr; cudaGetSymbolAddress(&cptr, g_cand_count);
    void* vptr = nullptr; cudaGetSymbolAddress(&vptr, g_validmask);
    cudaMemsetAsync(hptr, 0, NBINS * sizeof(unsigned));
    cudaMemsetAsync(cptr, 0, sizeof(unsigned));
    cudaMemsetAsync(vptr, 0, 32 * sizeof(unsigned));

    size_t seg_elems = (size_t)C * VVOX;

    hist_kernel<<<(N + 255) / 256, 256>>>(bb, N);
    thresh_kernel<<<1, 1024>>>();
    gather_kernel<<<(N + 255) / 256, 256>>>(bb, N);
    rank_kernel<<<(CAND_CAP * 32 + 1023) / 1024, 1024>>>(bb, labels);
    sup_kernel<<<K_PRE, 32>>>();
    final_kernel<<<1, 32>>>(out + seg_elems, out + seg_elems + MAX_OUT * 8);

    seg_kernel<<<(VVOX / 4 + 255) / 256, 256>>>(tiles, w, out, C);
}

// round 8
// speedup vs baseline: 1.7960x; 1.3704x over previous
#include <cuda_runtime.h>
#include <stdint.h>

#define IMGD   192
#define PATCHD 96
#define PVOX   (PATCHD*PATCHD*PATCHD)         // 884736
#define VVOX   (IMGD*IMGD*IMGD)               // 7077888
#define K_PRE  1000
#define MAX_OUT 100
#define NBINS  65536
#define CAND_CAP 2048
#define STAGE_ROWS 256
#define SCORE_THR 0.01f
#define MIN_SIZE  0.01f
#define IOU_THR   0.1f
#define CLS_OFF   384.0f   // 2.0 * 192.0

// ---------------- device scratch (no allocations allowed) ----------------
struct ClearBlk {
    unsigned hist[NBINS];
    unsigned cand_count;
    unsigned done;
    unsigned validmask[32];
};
__device__ ClearBlk           g_clr;
__device__ int                g_thresh_bin;
__device__ unsigned long long g_cands[CAND_CAP];
__device__ float              g_box [K_PRE*6];
__device__ float              g_obox[K_PRE*6];
__device__ float              g_sc  [K_PRE];
__device__ int                g_lab [K_PRE];
__device__ unsigned int       g_sup [K_PRE*32];

__device__ __forceinline__ unsigned fkey(float f) {
    unsigned u = __float_as_uint(f);
    return (u & 0x80000000u) ? ~u : (u | 0x80000000u);
}

// ---------------- seg ensemble kernel (closed-form coverage, float4) ----------------
__global__ void seg_kernel(const float* __restrict__ tiles,
                           const float* __restrict__ w,
                           float* __restrict__ out,
                           int C) {
    int v4 = blockIdx.x * blockDim.x + threadIdx.x;   // float4-group index
    if (v4 >= VVOX / 4) return;
    int zq = v4 % (IMGD / 4);
    int t2 = v4 / (IMGD / 4);
    int y  = t2 % IMGD;
    int x  = t2 / IMGD;
    int z  = zq * 4;

    int ix = (x >= 96) ? 2 : ((x >= 48) ? 1 : 0);
    int iy = (y >= 96) ? 2 : ((y >= 48) ? 1 : 0);
    int iz = (z >= 96) ? 2 : ((z >= 48) ? 1 : 0);
    bool two_x = (x >= 48) && (x < 144);
    bool two_y = (y >= 48) && (y < 144);
    bool two_z = (z >= 48) && (z < 144);

    int lx = x - ix * 48, ly = y - iy * 48, lz = z - iz * 48;
    int li = (lx * PATCHD + ly) * PATCHD + lz;

    float4 ws = make_float4(0.f, 0.f, 0.f, 0.f);
    float4 wl = make_float4(0.f, 0.f, 0.f, 0.f);
    #pragma unroll
    for (int a = 0; a < 2; a++) {
        if (a == 1 && !two_x) break;
        int xx = lx + a * 48;
        #pragma unroll
        for (int b = 0; b < 2; b++) {
            if (b == 1 && !two_y) break;
            int yy = ly + b * 48;
            #pragma unroll
            for (int cdim = 0; cdim < 2; cdim++) {
                if (cdim == 1 && !two_z) break;
                int zz = lz + cdim * 48;
                float4 wv = *reinterpret_cast<const float4*>(
                    w + (xx * PATCHD + yy) * PATCHD + zz);
                ws.x += wv.x; ws.y += wv.y; ws.z += wv.z; ws.w += wv.w;
                if (a == 0 && b == 0 && cdim == 0) wl = wv;
            }
        }
    }

    int tlast = ix * 9 + iy * 3 + iz;
    int v = v4 * 4;
    float4 inv = make_float4(wl.x / ws.x, wl.y / ws.y, wl.z / ws.z, wl.w / ws.w);
    for (int c = 0; c < C; c++) {
        float4 tv = *reinterpret_cast<const float4*>(
            tiles + (size_t)(tlast * C + c) * PVOX + li);
        float4 o;
        o.x = tv.x * inv.x; o.y = tv.y * inv.y;
        o.z = tv.z * inv.z; o.w = tv.w * inv.w;
        *reinterpret_cast<float4*>(out + (size_t)c * VVOX + v) = o;
    }
}

// ---------------- fused histogram + threshold (last-block-done) ----------------
__global__ void hist_thresh_kernel(const float* __restrict__ bb, int N) {
    int i = blockIdx.x * blockDim.x + threadIdx.x;
    if (i < N) {
        float s = __ldg(bb + (size_t)i * 7 + 6);
        atomicAdd(&g_clr.hist[fkey(s) >> 16], 1u);
    }
    __threadfence();
    __syncthreads();
    __shared__ int slast;
    if (threadIdx.x == 0)
        slast = (atomicAdd(&g_clr.done, 1u) == gridDim.x - 1) ? 1 : 0;
    __syncthreads();
    if (!slast) return;

    // last block: 256-thread suffix scan over 256 chunks of 256 bins
    __shared__ unsigned csum[256];
    int tid = threadIdx.x;
    unsigned s = 0;
    const uint4* hv = reinterpret_cast<const uint4*>(g_clr.hist) + tid * 64;
    #pragma unroll
    for (int q = 0; q < 64; q++) {
        uint4 v = hv[q];
        s += v.x + v.y + v.z + v.w;
    }
    csum[tid] = s;
    __syncthreads();
    for (int off = 1; off < 256; off <<= 1) {
        unsigned v = (tid + off < 256) ? csum[tid + off] : 0u;
        __syncthreads();
        csum[tid] += v;
        __syncthreads();
    }
    if (csum[tid] >= K_PRE && (tid == 255 || csum[tid + 1] < K_PRE)) {
        unsigned acc = (tid == 255) ? 0u : csum[tid + 1];
        int base = tid * 256;
        int bin = base;
        for (int b = 255; b >= 0; b--) {
            acc += g_clr.hist[base + b];
            if (acc >= K_PRE) { bin = base + b; break; }
        }
        g_thresh_bin = bin;
    }
}

__global__ void gather_kernel(const float* __restrict__ bb, int N) {
    int i = blockIdx.x * blockDim.x + threadIdx.x;
    if (i >= N) return;
    float s = __ldg(bb + (size_t)i * 7 + 6);
    unsigned key = fkey(s);
    if ((int)(key >> 16) >= g_thresh_bin) {
        unsigned pos = atomicAdd(&g_clr.cand_count, 1u);
        if (pos < CAND_CAP)
            g_cands[pos] = ((unsigned long long)key << 32) | (unsigned)(~(unsigned)i);
    }
}

// ---------------- rank by counting + prep (one warp per candidate, smem-staged) ----------------
__global__ void rank_kernel(const float* __restrict__ bb,
                            const int* __restrict__ labels) {
    __shared__ unsigned long long sc_[CAND_CAP];
    unsigned count = g_clr.cand_count;
    if (count > CAND_CAP) count = CAND_CAP;
    for (int k = threadIdx.x; k < (int)count; k += blockDim.x)
        sc_[k] = g_cands[k];
    __syncthreads();

    int gw   = (blockIdx.x * blockDim.x + threadIdx.x) >> 5;
    int lane = threadIdx.x & 31;
    if (gw >= (int)count) return;

    unsigned long long key = sc_[gw];
    int r = 0;
    for (int k = lane; k < (int)count; k += 32)
        r += (sc_[k] > key) ? 1 : 0;
    #pragma unroll
    for (int o = 16; o > 0; o >>= 1) r += __shfl_down_sync(0xffffffffu, r, o);
    r = __shfl_sync(0xffffffffu, r, 0);
    if (r >= K_PRE) return;

    if (lane == 0) {
        unsigned idx = ~((unsigned)key);
        const float* p = bb + (size_t)idx * 7;
        float sc = __ldg(p + 6);
        int lb = __ldg(labels + idx);
        float off = (float)lb * CLS_OFF;
        bool valid = sc > SCORE_THR;
        #pragma unroll
        for (int d = 0; d < 3; d++) {
            float lo = fminf(fmaxf(__ldg(p + d),     0.0f), (float)IMGD);
            float hi = fminf(fmaxf(__ldg(p + d + 3), 0.0f), (float)IMGD);
            g_box [r*6 + d]     = lo;
            g_box [r*6 + d + 3] = hi;
            g_obox[r*6 + d]     = lo + off;
            g_obox[r*6 + d + 3] = hi + off;
            valid = valid && ((hi - lo) >= MIN_SIZE);
        }
        g_sc[r] = sc;
        g_lab[r] = lb;
        if (valid) atomicOr(&g_clr.validmask[r >> 5], 1u << (r & 31));
    }
}

// ---------------- suppression bitmask (chip-wide parallel) ----------------
__global__ void sup_kernel() {
    int i = blockIdx.x;          // 0..K_PRE-1
    int t = threadIdx.x;         // 0..31 -> word index
    float a0 = g_obox[i*6+0], a1 = g_obox[i*6+1], a2 = g_obox[i*6+2];
    float a3 = g_obox[i*6+3], a4 = g_obox[i*6+4], a5 = g_obox[i*6+5];
    float va = ((a3 - a0) * (a4 - a1)) * (a5 - a2);
    unsigned m = 0;
    int base = t * 32;
    #pragma unroll 4
    for (int b = 0; b < 32; b++) {
        int j = base + b;
        if (j < K_PRE && j > i) {
            float b0 = g_obox[j*6+0], b1 = g_obox[j*6+1], b2 = g_obox[j*6+2];
            float b3 = g_obox[j*6+3], b4 = g_obox[j*6+4], b5 = g_obox[j*6+5];
            float cx = fmaxf(fminf(a3, b3) - fmaxf(a0, b0), 0.0f);
            float cy = fmaxf(fminf(a4, b4) - fmaxf(a1, b1), 0.0f);
            float cz = fmaxf(fminf(a5, b5) - fmaxf(a2, b2), 0.0f);
            float inter = (cx * cy) * cz;
            float vb = ((b3 - b0) * (b4 - b1)) * (b5 - b2);
            float uni = fmaxf(va + vb - inter, 1e-6f);
            if (inter / uni > IOU_THR) m |= (1u << b);
        }
    }
    g_sup[i*32 + t] = m;
}

// ---------------- final: stage first rows in static smem, 1-warp scan, emit ----------------
__global__ void final_kernel(float* __restrict__ dets,   // [100,8]
                             float* __restrict__ labs) { // [100]
    __shared__ unsigned ssup[STAGE_ROWS * 32];  // 32 KB static
    __shared__ int kept[MAX_OUT];
    int tid = threadIdx.x;
    for (int i = tid; i < STAGE_ROWS * 32; i += blockDim.x)
        ssup[i] = g_sup[i];
    __syncthreads();

    if (tid < 32) {
        int lane = tid;
        unsigned keepw = g_clr.validmask[lane];
        int nk = 0;
        for (int i = 0; i < K_PRE; i++) {
            unsigned w = __shfl_sync(0xffffffffu, keepw, i >> 5);
            if ((w >> (i & 31)) & 1u) {
                if (lane == 0) kept[nk] = i;
                nk++;
                if (nk == MAX_OUT) break;
                unsigned srow = (i < STAGE_ROWS) ? ssup[i*32 + lane] : g_sup[i*32 + lane];
                keepw &= ~srow;
            }
        }
        __syncwarp();
        for (int r = lane; r < MAX_OUT; r += 32) {
            if (r < nk) {
                int i = kept[r];
                #pragma unroll
                for (int d = 0; d < 6; d++) dets[r*8 + d] = g_box[i*6 + d];
                float s = g_sc[i];
                dets[r*8 + 6] = s;
                dets[r*8 + 7] = s;
                labs[r] = (float)g_lab[i];
            } else {
                #pragma unroll
                for (int d = 0; d < 8; d++) dets[r*8 + d] = 0.0f;
                labs[r] = -1.0f;
            }
        }
    }
}

// ---------------- launch (single stream, graph-capture safe) ----------------
extern "C" void kernel_launch(void* const* d_in, const int* in_sizes, int n_in,
                              void* d_out, int out_size) {
    const float* tiles  = (const float*)d_in[0];
    const float* w      = (const float*)d_in[1];
    const float* bb     = (const float*)d_in[2];
    const int*   labels = (const int*)  d_in[3];

    int T = in_sizes[4] / 3;
    int C = in_sizes[0] / (T * PVOX);
    int N = in_sizes[2] / 7;
    float* out = (float*)d_out;

    void* clrp = nullptr; cudaGetSymbolAddress(&clrp, g_clr);
    cudaMemsetAsync(clrp, 0, sizeof(ClearBlk));

    size_t seg_elems = (size_t)C * VVOX;

    hist_thresh_kernel<<<(N + 255) / 256, 256>>>(bb, N);
    gather_kernel<<<(N + 255) / 256, 256>>>(bb, N);
    rank_kernel<<<(CAND_CAP * 32 + 1023) / 1024, 1024>>>(bb, labels);
    sup_kernel<<<K_PRE, 32>>>();
    final_kernel<<<1, 1024>>>(out + seg_elems, out + seg_elems + MAX_OUT * 8);

    seg_kernel<<<(VVOX / 4 + 255) / 256, 256>>>(tiles, w, out, C);
}

// round 10
// speedup vs baseline: 1.8640x; 1.0378x over previous
#include <cuda_runtime.h>
#include <stdint.h>

#define IMGD   192
#define PATCHD 96
#define PVOX   (PATCHD*PATCHD*PATCHD)         // 884736
#define VVOX   (IMGD*IMGD*IMGD)               // 7077888
#define K_PRE  1000
#define MAX_OUT 100
#define NBINS  65536
#define CAND_CAP 2048
#define STAGE_ROWS 256
#define SCORE_THR 0.01f
#define MIN_SIZE  0.01f
#define IOU_THR   0.1f
#define CLS_OFF   384.0f   // 2.0 * 192.0

// ---------------- device scratch (no allocations allowed) ----------------
struct ClearBlk {
    unsigned hist[NBINS];
    unsigned cand_count;
    unsigned done;
    unsigned validmask[32];
};
__device__ ClearBlk           g_clr;
__device__ int                g_thresh_bin;
__device__ unsigned long long g_cands[CAND_CAP];
__device__ float              g_box [K_PRE*6];
__device__ float              g_obox[K_PRE*6];
__device__ float              g_sc  [K_PRE];
__device__ int                g_lab [K_PRE];
__device__ unsigned int       g_sup [K_PRE*32];

__device__ __forceinline__ unsigned fkey(float f) {
    unsigned u = __float_as_uint(f);
    return (u & 0x80000000u) ? ~u : (u | 0x80000000u);
}

// ---------------- seg ensemble kernel (closed-form coverage, float4) ----------------
__global__ void seg_kernel(const float* __restrict__ tiles,
                           const float* __restrict__ w,
                           float* __restrict__ out,
                           int C) {
    int v4 = blockIdx.x * blockDim.x + threadIdx.x;   // float4-group index
    if (v4 >= VVOX / 4) return;
    int zq = v4 % (IMGD / 4);
    int t2 = v4 / (IMGD / 4);
    int y  = t2 % IMGD;
    int x  = t2 / IMGD;
    int z  = zq * 4;

    int ix = (x >= 96) ? 2 : ((x >= 48) ? 1 : 0);
    int iy = (y >= 96) ? 2 : ((y >= 48) ? 1 : 0);
    int iz = (z >= 96) ? 2 : ((z >= 48) ? 1 : 0);
    bool two_x = (x >= 48) && (x < 144);
    bool two_y = (y >= 48) && (y < 144);
    bool two_z = (z >= 48) && (z < 144);

    int lx = x - ix * 48, ly = y - iy * 48, lz = z - iz * 48;
    int li = (lx * PATCHD + ly) * PATCHD + lz;

    float4 ws = make_float4(0.f, 0.f, 0.f, 0.f);
    float4 wl = make_float4(0.f, 0.f, 0.f, 0.f);
    #pragma unroll
    for (int a = 0; a < 2; a++) {
        if (a == 1 && !two_x) break;
        int xx = lx + a * 48;
        #pragma unroll
        for (int b = 0; b < 2; b++) {
            if (b == 1 && !two_y) break;
            int yy = ly + b * 48;
            #pragma unroll
            for (int cdim = 0; cdim < 2; cdim++) {
                if (cdim == 1 && !two_z) break;
                int zz = lz + cdim * 48;
                float4 wv = *reinterpret_cast<const float4*>(
                    w + (xx * PATCHD + yy) * PATCHD + zz);
                ws.x += wv.x; ws.y += wv.y; ws.z += wv.z; ws.w += wv.w;
                if (a == 0 && b == 0 && cdim == 0) wl = wv;
            }
        }
    }

    int tlast = ix * 9 + iy * 3 + iz;
    int v = v4 * 4;
    float4 inv = make_float4(wl.x / ws.x, wl.y / ws.y, wl.z / ws.z, wl.w / ws.w);
    for (int c = 0; c < C; c++) {
        float4 tv = *reinterpret_cast<const float4*>(
            tiles + (size_t)(tlast * C + c) * PVOX + li);
        float4 o;
        o.x = tv.x * inv.x; o.y = tv.y * inv.y;
        o.z = tv.z * inv.z; o.w = tv.w * inv.w;
        *reinterpret_cast<float4*>(out + (size_t)c * VVOX + v) = o;
    }
}

// ---------------- fused histogram + threshold (last-block-done) ----------------
__global__ void hist_thresh_kernel(const float* __restrict__ bb, int N) {
    int i = blockIdx.x * blockDim.x + threadIdx.x;
    if (i < N) {
        float s = __ldg(bb + (size_t)i * 7 + 6);
        atomicAdd(&g_clr.hist[fkey(s) >> 16], 1u);
    }
    __threadfence();
    __syncthreads();
    __shared__ int slast;
    if (threadIdx.x == 0)
        slast = (atomicAdd(&g_clr.done, 1u) == gridDim.x - 1) ? 1 : 0;
    __syncthreads();
    if (!slast) return;

    // last block: 256-thread suffix scan over 256 chunks of 256 bins
    __shared__ unsigned csum[256];
    int tid = threadIdx.x;
    unsigned s = 0;
    const uint4* hv = reinterpret_cast<const uint4*>(g_clr.hist) + tid * 64;
    #pragma unroll
    for (int q = 0; q < 64; q++) {
        uint4 v = hv[q];
        s += v.x + v.y + v.z + v.w;
    }
    csum[tid] = s;
    __syncthreads();
    for (int off = 1; off < 256; off <<= 1) {
        unsigned v = (tid + off < 256) ? csum[tid + off] : 0u;
        __syncthreads();
        csum[tid] += v;
        __syncthreads();
    }
    if (csum[tid] >= K_PRE && (tid == 255 || csum[tid + 1] < K_PRE)) {
        unsigned acc = (tid == 255) ? 0u : csum[tid + 1];
        int base = tid * 256;
        int bin = base;
        for (int b = 255; b >= 0; b--) {
            acc += g_clr.hist[base + b];
            if (acc >= K_PRE) { bin = base + b; break; }
        }
        g_thresh_bin = bin;
    }
}

__global__ void gather_kernel(const float* __restrict__ bb, int N) {
    int i = blockIdx.x * blockDim.x + threadIdx.x;
    if (i >= N) return;
    float s = __ldg(bb + (size_t)i * 7 + 6);
    unsigned key = fkey(s);
    if ((int)(key >> 16) >= g_thresh_bin) {
        unsigned pos = atomicAdd(&g_clr.cand_count, 1u);
        if (pos < CAND_CAP)
            g_cands[pos] = ((unsigned long long)key << 32) | (unsigned)(~(unsigned)i);
    }
}

// ---------------- rank by counting + prep (one warp per candidate, smem-staged) ----------------
__global__ void rank_kernel(const float* __restrict__ bb,
                            const int* __restrict__ labels) {
    __shared__ unsigned long long sc_[CAND_CAP];
    unsigned count = g_clr.cand_count;
    if (count > CAND_CAP) count = CAND_CAP;
    for (int k = threadIdx.x; k < (int)count; k += blockDim.x)
        sc_[k] = g_cands[k];
    __syncthreads();

    int gw   = (blockIdx.x * blockDim.x + threadIdx.x) >> 5;
    int lane = threadIdx.x & 31;
    if (gw >= (int)count) return;

    unsigned long long key = sc_[gw];
    int r = 0;
    for (int k = lane; k < (int)count; k += 32)
        r += (sc_[k] > key) ? 1 : 0;
    #pragma unroll
    for (int o = 16; o > 0; o >>= 1) r += __shfl_down_sync(0xffffffffu, r, o);
    r = __shfl_sync(0xffffffffu, r, 0);
    if (r >= K_PRE) return;

    if (lane == 0) {
        unsigned idx = ~((unsigned)key);
        const float* p = bb + (size_t)idx * 7;
        float sc = __ldg(p + 6);
        int lb = __ldg(labels + idx);
        float off = (float)lb * CLS_OFF;
        bool valid = sc > SCORE_THR;
        #pragma unroll
        for (int d = 0; d < 3; d++) {
            float lo = fminf(fmaxf(__ldg(p + d),     0.0f), (float)IMGD);
            float hi = fminf(fmaxf(__ldg(p + d + 3), 0.0f), (float)IMGD);
            g_box [r*6 + d]     = lo;
            g_box [r*6 + d + 3] = hi;
            g_obox[r*6 + d]     = lo + off;
            g_obox[r*6 + d + 3] = hi + off;
            valid = valid && ((hi - lo) >= MIN_SIZE);
        }
        g_sc[r] = sc;
        g_lab[r] = lb;
        if (valid) atomicOr(&g_clr.validmask[r >> 5], 1u << (r & 31));
    }
}

// ---------------- suppression bitmask (125 blocks x 256 threads, smem-staged) ----------------
__global__ void sup_kernel() {
    __shared__ float sbx[K_PRE * 6];   // 24 KB
    for (int k = threadIdx.x; k < K_PRE * 6; k += blockDim.x)
        sbx[k] = g_obox[k];
    __syncthreads();

    int gid = blockIdx.x * blockDim.x + threadIdx.x;   // 0..31999
    if (gid >= K_PRE * 32) return;
    int i = gid >> 5;
    int t = gid & 31;

    float a0 = sbx[i*6+0], a1 = sbx[i*6+1], a2 = sbx[i*6+2];
    float a3 = sbx[i*6+3], a4 = sbx[i*6+4], a5 = sbx[i*6+5];
    float va = ((a3 - a0) * (a4 - a1)) * (a5 - a2);
    unsigned m = 0;
    int base = t * 32;
    #pragma unroll 4
    for (int b = 0; b < 32; b++) {
        int j = base + b;
        if (j < K_PRE && j > i) {
            float b0 = sbx[j*6+0], b1 = sbx[j*6+1], b2 = sbx[j*6+2];
            float b3 = sbx[j*6+3], b4 = sbx[j*6+4], b5 = sbx[j*6+5];
            float cx = fmaxf(fminf(a3, b3) - fmaxf(a0, b0), 0.0f);
            float cy = fmaxf(fminf(a4, b4) - fmaxf(a1, b1), 0.0f);
            float cz = fmaxf(fminf(a5, b5) - fmaxf(a2, b2), 0.0f);
            float inter = (cx * cy) * cz;
            float vb = ((b3 - b0) * (b4 - b1)) * (b5 - b2);
            float uni = fmaxf(va + vb - inter, 1e-6f);
            if (inter / uni > IOU_THR) m |= (1u << b);
        }
    }
    g_sup[gid] = m;
}

// ---------------- final: stage first rows in static smem, 1-warp scan, emit ----------------
__global__ void final_kernel(float* __restrict__ dets,   // [100,8]
                             float* __restrict__ labs) { // [100]
    __shared__ unsigned ssup[STAGE_ROWS * 32];  // 32 KB static
    __shared__ int kept[MAX_OUT];
    int tid = threadIdx.x;
    for (int i = tid; i < STAGE_ROWS * 32; i += blockDim.x)
        ssup[i] = g_sup[i];
    __syncthreads();

    if (tid < 32) {
        int lane = tid;
        unsigned keepw = g_clr.validmask[lane];
        int nk = 0;
        for (int i = 0; i < K_PRE; i++) {
            unsigned w = __shfl_sync(0xffffffffu, keepw, i >> 5);
            if ((w >> (i & 31)) & 1u) {
                if (lane == 0) kept[nk] = i;
                nk++;
                if (nk == MAX_OUT) break;
                unsigned srow = (i < STAGE_ROWS) ? ssup[i*32 + lane] : g_sup[i*32 + lane];
                keepw &= ~srow;
            }
        }
        __syncwarp();
        for (int r = lane; r < MAX_OUT; r += 32) {
            if (r < nk) {
                int i = kept[r];
                #pragma unroll
                for (int d = 0; d < 6; d++) dets[r*8 + d] = g_box[i*6 + d];
                float s = g_sc[i];
                dets[r*8 + 6] = s;
                dets[r*8 + 7] = s;
                labs[r] = (float)g_lab[i];
            } else {
                #pragma unroll
                for (int d = 0; d < 8; d++) dets[r*8 + d] = 0.0f;
                labs[r] = -1.0f;
            }
        }
    }
}

// ---------------- launch (single stream, graph-capture safe) ----------------
extern "C" void kernel_launch(void* const* d_in, const int* in_sizes, int n_in,
                              void* d_out, int out_size) {
    const float* tiles  = (const float*)d_in[0];
    const float* w      = (const float*)d_in[1];
    const float* bb     = (const float*)d_in[2];
    const int*   labels = (const int*)  d_in[3];

    int T = in_sizes[4] / 3;
    int C = in_sizes[0] / (T * PVOX);
    int N = in_sizes[2] / 7;
    float* out = (float*)d_out;

    void* clrp = nullptr; cudaGetSymbolAddress(&clrp, g_clr);
    cudaMemsetAsync(clrp, 0, sizeof(ClearBlk));

    size_t seg_elems = (size_t)C * VVOX;

    hist_thresh_kernel<<<(N + 255) / 256, 256>>>(bb, N);
    gather_kernel<<<(N + 255) / 256, 256>>>(bb, N);
    rank_kernel<<<(CAND_CAP * 32 + 1023) / 1024, 1024>>>(bb, labels);
    sup_kernel<<<(K_PRE * 32 + 255) / 256, 256>>>();
    final_kernel<<<1, 1024>>>(out + seg_elems, out + seg_elems + MAX_OUT * 8);

    seg_kernel<<<(VVOX / 4 + 255) / 256, 256>>>(tiles, w, out, C);
}

// round 12
// speedup vs baseline: 2.0635x; 1.1070x over previous
#include <cuda_runtime.h>
#include <stdint.h>

#define IMGD   192
#define PATCHD 96
#define PVOX   (PATCHD*PATCHD*PATCHD)         // 884736
#define VVOX   (IMGD*IMGD*IMGD)               // 7077888
#define K_PRE  1000
#define MAX_OUT 100
#define NBINS  65536
#define CAND_CAP 2048
#define STAGE_ROWS 256
#define SCORE_THR 0.01f
#define MIN_SIZE  0.01f
#define IOU_THR   0.1f
#define CLS_OFF   384.0f   // 2.0 * 192.0

// ---------------- device scratch (no allocations allowed) ----------------
struct ClearBlk {
    unsigned hist[NBINS];
    unsigned cand_count;
    unsigned done;
    unsigned validmask[32];
};
__device__ ClearBlk           g_clr;
__device__ int                g_thresh_bin;
__device__ unsigned long long g_cands[CAND_CAP];
__device__ float              g_box [K_PRE*6];
__device__ float              g_obox[K_PRE*6];
__device__ float              g_sc  [K_PRE];
__device__ int                g_lab [K_PRE];
__device__ unsigned int       g_sup [K_PRE*32];

__device__ __forceinline__ unsigned fkey(float f) {
    unsigned u = __float_as_uint(f);
    return (u & 0x80000000u) ? ~u : (u | 0x80000000u);
}

// ---------------- seg ensemble kernel (closed-form coverage, float4) ----------------
__global__ void seg_kernel(const float* __restrict__ tiles,
                           const float* __restrict__ w,
                           float* __restrict__ out,
                           int C) {
    int v4 = blockIdx.x * blockDim.x + threadIdx.x;   // float4-group index
    if (v4 >= VVOX / 4) return;
    int zq = v4 % (IMGD / 4);
    int t2 = v4 / (IMGD / 4);
    int y  = t2 % IMGD;
    int x  = t2 / IMGD;
    int z  = zq * 4;

    int ix = (x >= 96) ? 2 : ((x >= 48) ? 1 : 0);
    int iy = (y >= 96) ? 2 : ((y >= 48) ? 1 : 0);
    int iz = (z >= 96) ? 2 : ((z >= 48) ? 1 : 0);
    bool two_x = (x >= 48) && (x < 144);
    bool two_y = (y >= 48) && (y < 144);
    bool two_z = (z >= 48) && (z < 144);

    int lx = x - ix * 48, ly = y - iy * 48, lz = z - iz * 48;
    int li = (lx * PATCHD + ly) * PATCHD + lz;

    float4 ws = make_float4(0.f, 0.f, 0.f, 0.f);
    float4 wl = make_float4(0.f, 0.f, 0.f, 0.f);
    #pragma unroll
    for (int a = 0; a < 2; a++) {
        if (a == 1 && !two_x) break;
        int xx = lx + a * 48;
        #pragma unroll
        for (int b = 0; b < 2; b++) {
            if (b == 1 && !two_y) break;
            int yy = ly + b * 48;
            #pragma unroll
            for (int cdim = 0; cdim < 2; cdim++) {
                if (cdim == 1 && !two_z) break;
                int zz = lz + cdim * 48;
                float4 wv = *reinterpret_cast<const float4*>(
                    w + (xx * PATCHD + yy) * PATCHD + zz);
                ws.x += wv.x; ws.y += wv.y; ws.z += wv.z; ws.w += wv.w;
                if (a == 0 && b == 0 && cdim == 0) wl = wv;
            }
        }
    }

    int tlast = ix * 9 + iy * 3 + iz;
    int v = v4 * 4;
    float4 inv = make_float4(wl.x / ws.x, wl.y / ws.y, wl.z / ws.z, wl.w / ws.w);
    for (int c = 0; c < C; c++) {
        float4 tv = *reinterpret_cast<const float4*>(
            tiles + (size_t)(tlast * C + c) * PVOX + li);
        float4 o;
        o.x = tv.x * inv.x; o.y = tv.y * inv.y;
        o.z = tv.z * inv.z; o.w = tv.w * inv.w;
        *reinterpret_cast<float4*>(out + (size_t)c * VVOX + v) = o;
    }
}

// ---------------- fused histogram + threshold (last-block-done) ----------------
__global__ void hist_thresh_kernel(const float* __restrict__ bb, int N) {
    int i = blockIdx.x * blockDim.x + threadIdx.x;
    if (i < N) {
        float s = __ldg(bb + (size_t)i * 7 + 6);
        atomicAdd(&g_clr.hist[fkey(s) >> 16], 1u);
    }
    __threadfence();
    __syncthreads();
    __shared__ int slast;
    if (threadIdx.x == 0)
        slast = (atomicAdd(&g_clr.done, 1u) == gridDim.x - 1) ? 1 : 0;
    __syncthreads();
    if (!slast) return;

    // last block: 256-thread suffix scan over 256 chunks of 256 bins
    __shared__ unsigned csum[256];
    int tid = threadIdx.x;
    unsigned s = 0;
    const uint4* hv = reinterpret_cast<const uint4*>(g_clr.hist) + tid * 64;
    #pragma unroll
    for (int q = 0; q < 64; q++) {
        uint4 v = hv[q];
        s += v.x + v.y + v.z + v.w;
    }
    csum[tid] = s;
    __syncthreads();
    for (int off = 1; off < 256; off <<= 1) {
        unsigned v = (tid + off < 256) ? csum[tid + off] : 0u;
        __syncthreads();
        csum[tid] += v;
        __syncthreads();
    }
    if (csum[tid] >= K_PRE && (tid == 255 || csum[tid + 1] < K_PRE)) {
        unsigned acc = (tid == 255) ? 0u : csum[tid + 1];
        int base = tid * 256;
        int bin = base;
        for (int b = 255; b >= 0; b--) {
            acc += g_clr.hist[base + b];
            if (acc >= K_PRE) { bin = base + b; break; }
        }
        g_thresh_bin = bin;
    }
}

__global__ void gather_kernel(const float* __restrict__ bb, int N) {
    int i = blockIdx.x * blockDim.x + threadIdx.x;
    if (i >= N) return;
    float s = __ldg(bb + (size_t)i * 7 + 6);
    unsigned key = fkey(s);
    if ((int)(key >> 16) >= g_thresh_bin) {
        unsigned pos = atomicAdd(&g_clr.cand_count, 1u);
        if (pos < CAND_CAP)
            g_cands[pos] = ((unsigned long long)key << 32) | (unsigned)(~(unsigned)i);
    }
}

// ---------------- rank by counting + prep (one warp per candidate, smem-staged) ----------------
__global__ void rank_kernel(const float* __restrict__ bb,
                            const int* __restrict__ labels) {
    __shared__ unsigned long long sc_[CAND_CAP];
    unsigned count = g_clr.cand_count;
    if (count > CAND_CAP) count = CAND_CAP;
    for (int k = threadIdx.x; k < (int)count; k += blockDim.x)
        sc_[k] = g_cands[k];
    __syncthreads();

    int gw   = (blockIdx.x * blockDim.x + threadIdx.x) >> 5;
    int lane = threadIdx.x & 31;
    if (gw >= (int)count) return;

    unsigned long long key = sc_[gw];
    int r = 0;
    for (int k = lane; k < (int)count; k += 32)
        r += (sc_[k] > key) ? 1 : 0;
    #pragma unroll
    for (int o = 16; o > 0; o >>= 1) r += __shfl_down_sync(0xffffffffu, r, o);
    r = __shfl_sync(0xffffffffu, r, 0);
    if (r >= K_PRE) return;

    if (lane == 0) {
        unsigned idx = ~((unsigned)key);
        const float* p = bb + (size_t)idx * 7;
        float sc = __ldg(p + 6);
        int lb = __ldg(labels + idx);
        float off = (float)lb * CLS_OFF;
        bool valid = sc > SCORE_THR;
        #pragma unroll
        for (int d = 0; d < 3; d++) {
            float lo = fminf(fmaxf(__ldg(p + d),     0.0f), (float)IMGD);
            float hi = fminf(fmaxf(__ldg(p + d + 3), 0.0f), (float)IMGD);
            g_box [r*6 + d]     = lo;
            g_box [r*6 + d + 3] = hi;
            g_obox[r*6 + d]     = lo + off;
            g_obox[r*6 + d + 3] = hi + off;
            valid = valid && ((hi - lo) >= MIN_SIZE);
        }
        g_sc[r] = sc;
        g_lab[r] = lb;
        if (valid) atomicOr(&g_clr.validmask[r >> 5], 1u << (r & 31));
    }
}

// ---------------- suppression bitmask (one block per row, ballot, no smem) ----------------
__global__ void sup_kernel() {
    int i = blockIdx.x;                 // row 0..K_PRE-1
    int wrp = threadIdx.x >> 5;         // 0..7
    int lane = threadIdx.x & 31;

    float a0 = __ldg(&g_obox[i*6+0]), a1 = __ldg(&g_obox[i*6+1]), a2 = __ldg(&g_obox[i*6+2]);
    float a3 = __ldg(&g_obox[i*6+3]), a4 = __ldg(&g_obox[i*6+4]), a5 = __ldg(&g_obox[i*6+5]);
    float va = ((a3 - a0) * (a4 - a1)) * (a5 - a2);

    #pragma unroll
    for (int wq = 0; wq < 4; wq++) {
        int word = wrp + wq * 8;        // 0..31
        int j = word * 32 + lane;
        bool sup = false;
        if (j < K_PRE && j > i) {
            float b0 = __ldg(&g_obox[j*6+0]), b1 = __ldg(&g_obox[j*6+1]), b2 = __ldg(&g_obox[j*6+2]);
            float b3 = __ldg(&g_obox[j*6+3]), b4 = __ldg(&g_obox[j*6+4]), b5 = __ldg(&g_obox[j*6+5]);
            float cx = fmaxf(fminf(a3, b3) - fmaxf(a0, b0), 0.0f);
            float cy = fmaxf(fminf(a4, b4) - fmaxf(a1, b1), 0.0f);
            float cz = fmaxf(fminf(a5, b5) - fmaxf(a2, b2), 0.0f);
            float inter = (cx * cy) * cz;
            float vb = ((b3 - b0) * (b4 - b1)) * (b5 - b2);
            float uni = fmaxf(va + vb - inter, 1e-6f);
            sup = (inter / uni > IOU_THR);
        }
        unsigned m = __ballot_sync(0xffffffffu, sup);
        if (lane == 0) g_sup[i*32 + word] = m;
    }
}

// ---------------- final: stage first rows in static smem, 1-warp scan, emit ----------------
__global__ void final_kernel(float* __restrict__ dets,   // [100,8]
                             float* __restrict__ labs) { // [100]
    __shared__ unsigned ssup[STAGE_ROWS * 32];  // 32 KB static
    __shared__ int kept[MAX_OUT];
    int tid = threadIdx.x;
    for (int i = tid; i < STAGE_ROWS * 32; i += blockDim.x)
        ssup[i] = g_sup[i];
    __syncthreads();

    if (tid < 32) {
        int lane = tid;
        unsigned keepw = g_clr.validmask[lane];
        int nk = 0;
        for (int i = 0; i < K_PRE; i++) {
            unsigned w = __shfl_sync(0xffffffffu, keepw, i >> 5);
            if ((w >> (i & 31)) & 1u) {
                if (lane == 0) kept[nk] = i;
                nk++;
                if (nk == MAX_OUT) break;
                unsigned srow = (i < STAGE_ROWS) ? ssup[i*32 + lane] : g_sup[i*32 + lane];
                keepw &= ~srow;
            }
        }
        __syncwarp();
        for (int r = lane; r < MAX_OUT; r += 32) {
            if (r < nk) {
                int i = kept[r];
                #pragma unroll
                for (int d = 0; d < 6; d++) dets[r*8 + d] = g_box[i*6 + d];
                float s = g_sc[i];
                dets[r*8 + 6] = s;
                dets[r*8 + 7] = s;
                labs[r] = (float)g_lab[i];
            } else {
                #pragma unroll
                for (int d = 0; d < 8; d++) dets[r*8 + d] = 0.0f;
                labs[r] = -1.0f;
            }
        }
    }
}

// ---------------- launch (single stream, graph-capture safe) ----------------
extern "C" void kernel_launch(void* const* d_in, const int* in_sizes, int n_in,
                              void* d_out, int out_size) {
    const float* tiles  = (const float*)d_in[0];
    const float* w      = (const float*)d_in[1];
    const float* bb     = (const float*)d_in[2];
    const int*   labels = (const int*)  d_in[3];

    int T = in_sizes[4] / 3;
    int C = in_sizes[0] / (T * PVOX);
    int N = in_sizes[2] / 7;
    float* out = (float*)d_out;

    void* clrp = nullptr; cudaGetSymbolAddress(&clrp, g_clr);
    cudaMemsetAsync(clrp, 0, sizeof(ClearBlk));

    size_t seg_elems = (size_t)C * VVOX;

    hist_thresh_kernel<<<(N + 255) / 256, 256>>>(bb, N);
    gather_kernel<<<(N + 255) / 256, 256>>>(bb, N);
    rank_kernel<<<(CAND_CAP * 32 + 1023) / 1024, 1024>>>(bb, labels);
    sup_kernel<<<K_PRE, 256>>>();
    final_kernel<<<1, 1024>>>(out + seg_elems, out + seg_elems + MAX_OUT * 8);

    seg_kernel<<<(VVOX / 4 + 255) / 256, 256>>>(tiles, w, out, C);
}